// round 15
// baseline (speedup 1.0000x reference)
#include <cuda_runtime.h>
#include <cuda_fp16.h>
#include <math.h>
#include <stdint.h>

// ---------------------------------------------------------------------------
// Problem constants
// ---------------------------------------------------------------------------
#define BATCH     2
#define SEQ       8192
#define HID       1024
#define NHEADS    16
#define HDIM      64
#define KWIN      7
#define ATT_SCALE 0.125f
#define M_ROWS    (BATCH * SEQ)     // 16384

// ---------------------------------------------------------------------------
// Scratch (__device__ globals: allowed, no runtime allocation)
// ---------------------------------------------------------------------------
__device__ __half g_q[(size_t)M_ROWS * HID];
__device__ __half g_k[(size_t)M_ROWS * HID];
__device__ __half g_v[(size_t)M_ROWS * HID];
__device__ __half g_a[(size_t)M_ROWS * HID];      // fp16 A operand (reused)
__device__ __half g_w[(size_t)4 * HID * HID];     // transposed [n][k], fp16

// ---------------------------------------------------------------------------
// PTX helpers (base sm_103 target — NO 'a'-gated features)
// ---------------------------------------------------------------------------
__device__ __forceinline__ uint32_t smem_u32(const void* p) {
    uint32_t a;
    asm("{ .reg .u64 t; cvta.to.shared.u64 t, %1; cvt.u32.u64 %0, t; }"
        : "=r"(a) : "l"(p));
    return a;
}
__device__ __forceinline__ void cp16(uint32_t s, const void* g) {
    asm volatile("cp.async.cg.shared.global [%0], [%1], 16;"
                 :: "r"(s), "l"(g));
}
__device__ __forceinline__ void ldsm_x4(uint32_t* r, uint32_t addr) {
    asm volatile("ldmatrix.sync.aligned.m8n8.x4.shared.b16 {%0,%1,%2,%3}, [%4];"
                 : "=r"(r[0]), "=r"(r[1]), "=r"(r[2]), "=r"(r[3]) : "r"(addr));
}
__device__ __forceinline__ void ldsm_x4_t(uint32_t* r, uint32_t addr) {
    asm volatile("ldmatrix.sync.aligned.m8n8.x4.trans.shared.b16 {%0,%1,%2,%3}, [%4];"
                 : "=r"(r[0]), "=r"(r[1]), "=r"(r[2]), "=r"(r[3]) : "r"(addr));
}
__device__ __forceinline__ void mma16816(float* d, const uint32_t* a,
                                         const uint32_t* b) {
    asm volatile(
        "mma.sync.aligned.m16n8k16.row.col.f32.f16.f16.f32 "
        "{%0,%1,%2,%3}, {%4,%5,%6,%7}, {%8,%9}, {%0,%1,%2,%3};"
        : "+f"(d[0]), "+f"(d[1]), "+f"(d[2]), "+f"(d[3])
        : "r"(a[0]), "r"(a[1]), "r"(a[2]), "r"(a[3]), "r"(b[0]), "r"(b[1]));
}

// ---------------------------------------------------------------------------
// GEMM config: 128x128 CTA tile, BK=64, 2-stage cp.async ring, 128 threads
// (4 warps, 2x2 grid of 64x64 warp tiles), 2 CTAs per SM.
// 16 chunk barriers (vs 32 at BK=32); single __syncthreads per chunk.
// Pitch 144 B: 128 B data + 16 pad -> ldsm conflict-free (bank stride 36).
// ---------------------------------------------------------------------------
#define GPITCH  144
#define GTILE   (128 * GPITCH)          // 18432
#define GOFF_B  GTILE
#define GBUFB   (2 * GTILE)             // 36864 per stage (A + B)
#define GSMEM   (2 * GBUFB)             // 73728 (2 stages)

__device__ __forceinline__ void load_chunk(
    uint32_t base, int tid, int k0, int m0, int n0,
    const __half* __restrict__ A, const __half* __restrict__ B)
{
#pragma unroll
    for (int r = 0; r < 8; r++) {   // A: 128 rows x 128B = 1024 cp16
        int idx = tid + r * 128;
        int row = idx >> 3, c = idx & 7;
        uint32_t so = (uint32_t)(row * GPITCH + c * 16);
        size_t go = (size_t)(m0 + row) * HID + k0 + c * 8;
        cp16(base + so, A + go);
    }
#pragma unroll
    for (int r = 0; r < 8; r++) {   // B: 128 rows x 128B = 1024 cp16
        int idx = tid + r * 128;
        int row = idx >> 3, c = idx & 7;
        uint32_t so = (uint32_t)(row * GPITCH + c * 16);
        size_t go = (size_t)(n0 + row) * HID + k0 + c * 8;
        cp16(base + GOFF_B + so, B + go);
    }
    asm volatile("cp.async.commit_group;" ::: "memory");
}

// C[m][n] = sum_k A[m][k]*Wt[n][k] + bias[n], single-pass fp16 HMMA.
// grid.x: (matrix_within_launch << 3) | n_tile;  grid.y: m_tile
template <bool HALF_OUT>
__global__ void __launch_bounds__(128, 2)
gemm_mma(const __half* __restrict__ A, const __half* __restrict__ W,
         int mat_base,
         const float* __restrict__ bias0, const float* __restrict__ bias1,
         const float* __restrict__ bias2,
         void* __restrict__ c0v, void* __restrict__ c1v, void* __restrict__ c2v)
{
    extern __shared__ char smem[];
    const uint32_t sb = smem_u32(smem);
    const int tid  = threadIdx.x;
    const int lane = tid & 31;
    const int wid  = tid >> 5;          // 0..3
    const int wm   = wid >> 1;          // 0..1 -> 64-row slab
    const int wn   = wid & 1;           // 0..1 -> 64-col slab
    const int mi_  = blockIdx.x >> 3;   // matrix within launch
    const int n0   = (blockIdx.x & 7) * 128;
    const int m0   = blockIdx.y * 128;

    const __half* B = W + (size_t)(mat_base + mi_) * HID * HID;
    const float* bias = (mi_ == 0) ? bias0 : ((mi_ == 1) ? bias1 : bias2);
    void* Cv = (mi_ == 0) ? c0v : ((mi_ == 1) ? c1v : c2v);

    float acc[4][8][4];                 // 64x64 warp tile: mi x ni x frag
#pragma unroll
    for (int i = 0; i < 4; i++)
#pragma unroll
        for (int j = 0; j < 8; j++)
#pragma unroll
            for (int r = 0; r < 4; r++) acc[i][j][r] = 0.0f;

    // prologue: chunk 0 into stage 0
    load_chunk(sb, tid, 0, m0, n0, A, B);

    const int mrow = lane >> 3;
    const int jrow = lane & 7;
    const uint32_t a_off = (uint32_t)((wm * 64 + (mrow & 1) * 8 + jrow) * GPITCH
                                      + (mrow >> 1) * 16);
    const uint32_t b_off = (uint32_t)((wn * 64 + (mrow >> 1) * 8 + jrow) * GPITCH
                                      + (mrow & 1) * 16) + GOFF_B;

    const int NCHUNK = HID / 64;        // 16
    int st = 0;

    for (int ck = 0; ck < NCHUNK; ck++) {
        asm volatile("cp.async.wait_group 0;" ::: "memory");
        __syncthreads();   // chunk ck visible; all warps done with chunk ck-1

        // prefetch chunk ck+1 into the other stage (freed at iter ck-1);
        // lands during this chunk's ~2000-cycle compute
        if (ck + 1 < NCHUNK)
            load_chunk(sb + (st ^ 1) * GBUFB, tid, (ck + 1) * 64, m0, n0, A, B);

        const uint32_t base = sb + st * GBUFB;
#pragma unroll
        for (int ks = 0; ks < 4; ks++) {
            const uint32_t kb = ks * 32;
            uint32_t bf[4][4];          // 64 cols = 4 x ldsm.x4
#pragma unroll
            for (int nj = 0; nj < 4; nj++)
                ldsm_x4(bf[nj], base + b_off + nj * 16 * GPITCH + kb);
#pragma unroll
            for (int mi = 0; mi < 4; mi++) {
                uint32_t ah[4];
                ldsm_x4(ah, base + a_off + mi * 16 * GPITCH + kb);
#pragma unroll
                for (int ni = 0; ni < 8; ni++)
                    mma16816(acc[mi][ni], ah, &bf[ni >> 1][(ni & 1) * 2]);
            }
        }
        st ^= 1;
    }

    const int grp = lane >> 2, t4 = lane & 3;
#pragma unroll
    for (int ni = 0; ni < 8; ni++) {
        const int col = n0 + wn * 64 + ni * 8 + t4 * 2;
        const float bv0 = bias[col], bv1 = bias[col + 1];
#pragma unroll
        for (int mi = 0; mi < 4; mi++) {
            const int r0 = m0 + wm * 64 + mi * 16 + grp;
            if (HALF_OUT) {
                __half* C = (__half*)Cv;
                __half2 p0 = __floats2half2_rn(acc[mi][ni][0] + bv0,
                                               acc[mi][ni][1] + bv1);
                __half2 p1 = __floats2half2_rn(acc[mi][ni][2] + bv0,
                                               acc[mi][ni][3] + bv1);
                *(uint32_t*)(C + (size_t)r0 * HID + col)       = *(uint32_t*)&p0;
                *(uint32_t*)(C + (size_t)(r0 + 8) * HID + col) = *(uint32_t*)&p1;
            } else {
                float* C = (float*)Cv;
                *(float2*)(C + (size_t)r0 * HID + col) =
                    make_float2(acc[mi][ni][0] + bv0, acc[mi][ni][1] + bv1);
                *(float2*)(C + (size_t)(r0 + 8) * HID + col) =
                    make_float2(acc[mi][ni][2] + bv0, acc[mi][ni][3] + bv1);
            }
        }
    }
}

// ---------------------------------------------------------------------------
// Fused prep: blocks [0,16384) convert activations fp32->fp16;
// blocks [16384,20480) transpose+round the 4 weight matrices.
// ---------------------------------------------------------------------------
#define CONV_BLOCKS 16384
#define PREP_BLOCKS (CONV_BLOCKS + 4096)

__global__ void __launch_bounds__(256)
prep_kernel(const float* __restrict__ x, __half* __restrict__ y,
            const float* __restrict__ w0, const float* __restrict__ w1,
            const float* __restrict__ w2, const float* __restrict__ w3,
            __half* __restrict__ wt)
{
    __shared__ float t[32][33];
    if (blockIdx.x < CONV_BLOCKS) {
        size_t i = ((size_t)blockIdx.x * 256 + threadIdx.x) * 4;
        float4 v = *(const float4*)(x + i);
        __half2 p0 = __floats2half2_rn(v.x, v.y);
        __half2 p1 = __floats2half2_rn(v.z, v.w);
        *(uint2*)(y + i) = make_uint2(*(uint32_t*)&p0, *(uint32_t*)&p1);
    } else {
        const int bid = blockIdx.x - CONV_BLOCKS;
        const int z = bid >> 10;
        const int rem = bid & 1023;
        const int n0 = (rem & 31) * 32, k0 = (rem >> 5) * 32;
        const float* W = (z == 0) ? w0 : ((z == 1) ? w1 : ((z == 2) ? w2 : w3));
        const int tx = threadIdx.x & 31, ty = threadIdx.x >> 5;
#pragma unroll
        for (int r = 0; r < 4; r++)
            t[ty + r * 8][tx] = W[(size_t)(k0 + ty + r * 8) * HID + n0 + tx];
        __syncthreads();
        const size_t base = (size_t)z * HID * HID;
#pragma unroll
        for (int r = 0; r < 4; r++) {
            int n = n0 + ty + r * 8;
            int k = k0 + tx;
            wt[base + (size_t)n * HID + k] = __float2half_rn(t[tx][ty + r * 8]);
        }
    }
}

// ---------------------------------------------------------------------------
// HMMA neighborhood attention (two-group staging; unchanged from R12-R14)
// ---------------------------------------------------------------------------
#define PV      144
#define ASMEM   ((128 + 144 + 144) * PV)    // 59904

__global__ void __launch_bounds__(256)
attn_mma(const __half* __restrict__ Q, const __half* __restrict__ K,
         const __half* __restrict__ V, __half* __restrict__ O)
{
    extern __shared__ char smem[];
    const uint32_t sbq = smem_u32(smem);
    const uint32_t sbk = sbq + 128 * PV;
    const uint32_t sbv = sbk + 144 * PV;
    const int tid = threadIdx.x, lane = tid & 31, w = tid >> 5;
    const int bh = blockIdx.x >> 6;
    const int s0 = (blockIdx.x & 63) * 128;
    const int b = bh >> 4, h = bh & 15;
    const size_t rowbase = ((size_t)b * SEQ) * HID + h * HDIM;

#pragma unroll
    for (int r = 0; r < 4; r++) {
        int idx = tid + r * 256;
        int row = idx >> 3, c = idx & 7;
        cp16(sbq + row * PV + c * 16,
             Q + rowbase + (size_t)(s0 + row) * HID + c * 8);
    }
    for (int idx = tid; idx < 1152; idx += 256) {
        int row = idx >> 3, c = idx & 7;
        int sk = s0 + row - 3;
        sk = sk < 0 ? 0 : (sk >= SEQ ? SEQ - 1 : sk);
        cp16(sbk + row * PV + c * 16, K + rowbase + (size_t)sk * HID + c * 8);
    }
    asm volatile("cp.async.commit_group;" ::: "memory");
    for (int idx = tid; idx < 1152; idx += 256) {
        int row = idx >> 3, c = idx & 7;
        int sk = s0 + row - 3;
        sk = sk < 0 ? 0 : (sk >= SEQ ? SEQ - 1 : sk);
        cp16(sbv + row * PV + c * 16, V + rowbase + (size_t)sk * HID + c * 8);
    }
    asm volatile("cp.async.commit_group;" ::: "memory");
    asm volatile("cp.async.wait_group 1;" ::: "memory");
    __syncthreads();

    const int mrow = lane >> 3, jrow = lane & 7;
    const int grp = lane >> 2, t4 = lane & 3;
    const uint32_t aq_off = sbq + (uint32_t)((w * 16 + (mrow & 1) * 8 + jrow) * PV
                                             + (mrow >> 1) * 16);
    const uint32_t bk_off = sbk + (uint32_t)((w * 16 + (mrow >> 1) * 8 + jrow) * PV
                                             + (mrow & 1) * 16);
    const uint32_t bv_off = sbv + (uint32_t)((w * 16 + (mrow & 1) * 8 + jrow) * PV
                                             + (mrow >> 1) * 16);

    float accS[4][4];
#pragma unroll
    for (int i = 0; i < 4; i++)
#pragma unroll
        for (int r = 0; r < 4; r++) accS[i][r] = 0.0f;

#pragma unroll
    for (int ks = 0; ks < 4; ks++) {
        uint32_t aq[4], bk0[4], bk1[4];
        ldsm_x4(aq,  aq_off + ks * 32);
        ldsm_x4(bk0, bk_off + ks * 32);
        ldsm_x4(bk1, bk_off + 16 * PV + ks * 32);
        mma16816(accS[0], aq, &bk0[0]);
        mma16816(accS[1], aq, &bk0[2]);
        mma16816(accS[2], aq, &bk1[0]);
        mma16816(accS[3], aq, &bk1[2]);
    }

    const float NEG = -1e30f;
#pragma unroll
    for (int ni = 0; ni < 4; ni++)
#pragma unroll
        for (int pp = 0; pp < 4; pp++) {
            int r = (pp >= 2) ? grp + 8 : grp;
            int c = 8 * ni + 2 * t4 + (pp & 1);
            int sk = s0 + 16 * w + c - 3;
            bool ok = (c >= r) && (c <= r + 6) && (sk >= 0) && (sk < SEQ);
            accS[ni][pp] = ok ? accS[ni][pp] * ATT_SCALE : NEG;
        }

    float m0 = NEG, m1 = NEG;
#pragma unroll
    for (int ni = 0; ni < 4; ni++) {
        m0 = fmaxf(m0, fmaxf(accS[ni][0], accS[ni][1]));
        m1 = fmaxf(m1, fmaxf(accS[ni][2], accS[ni][3]));
    }
#pragma unroll
    for (int o = 1; o <= 2; o <<= 1) {
        m0 = fmaxf(m0, __shfl_xor_sync(0xffffffffu, m0, o));
        m1 = fmaxf(m1, __shfl_xor_sync(0xffffffffu, m1, o));
    }
    float d0 = 0.0f, d1 = 0.0f;
#pragma unroll
    for (int ni = 0; ni < 4; ni++) {
        accS[ni][0] = __expf(accS[ni][0] - m0);
        accS[ni][1] = __expf(accS[ni][1] - m0);
        accS[ni][2] = __expf(accS[ni][2] - m1);
        accS[ni][3] = __expf(accS[ni][3] - m1);
        d0 += accS[ni][0] + accS[ni][1];
        d1 += accS[ni][2] + accS[ni][3];
    }
#pragma unroll
    for (int o = 1; o <= 2; o <<= 1) {
        d0 += __shfl_xor_sync(0xffffffffu, d0, o);
        d1 += __shfl_xor_sync(0xffffffffu, d1, o);
    }
    const float inv0 = 1.0f / d0, inv1 = 1.0f / d1;

    uint32_t aP[2][4];
#pragma unroll
    for (int ks = 0; ks < 2; ks++) {
        __half2 v0 = __floats2half2_rn(accS[2 * ks][0] * inv0,
                                       accS[2 * ks][1] * inv0);
        __half2 v1 = __floats2half2_rn(accS[2 * ks][2] * inv1,
                                       accS[2 * ks][3] * inv1);
        __half2 v2 = __floats2half2_rn(accS[2 * ks + 1][0] * inv0,
                                       accS[2 * ks + 1][1] * inv0);
        __half2 v3 = __floats2half2_rn(accS[2 * ks + 1][2] * inv1,
                                       accS[2 * ks + 1][3] * inv1);
        aP[ks][0] = *(uint32_t*)&v0;
        aP[ks][1] = *(uint32_t*)&v1;
        aP[ks][2] = *(uint32_t*)&v2;
        aP[ks][3] = *(uint32_t*)&v3;
    }

    asm volatile("cp.async.wait_group 0;" ::: "memory");
    __syncthreads();

    float accO[8][4];
#pragma unroll
    for (int i = 0; i < 8; i++)
#pragma unroll
        for (int r = 0; r < 4; r++) accO[i][r] = 0.0f;

#pragma unroll
    for (int g = 0; g < 4; g++)
#pragma unroll
        for (int ks = 0; ks < 2; ks++) {
            uint32_t bv[4];
            ldsm_x4_t(bv, bv_off + ks * 16 * PV + g * 32);
            mma16816(accO[2 * g],     aP[ks], &bv[0]);
            mma16816(accO[2 * g + 1], aP[ks], &bv[2]);
        }

    const int q0 = s0 + 16 * w;
#pragma unroll
    for (int nf = 0; nf < 8; nf++) {
        int col = 8 * nf + 2 * t4;
        __half2 p0 = __floats2half2_rn(accO[nf][0], accO[nf][1]);
        __half2 p1 = __floats2half2_rn(accO[nf][2], accO[nf][3]);
        *(uint32_t*)(O + rowbase + (size_t)(q0 + grp) * HID + col)     = *(uint32_t*)&p0;
        *(uint32_t*)(O + rowbase + (size_t)(q0 + grp + 8) * HID + col) = *(uint32_t*)&p1;
    }
}

// ---------------------------------------------------------------------------
// Launch
// ---------------------------------------------------------------------------
extern "C" void kernel_launch(void* const* d_in, const int* in_sizes, int n_in,
                              void* d_out, int out_size)
{
    const float* hs  = (const float*)d_in[0];
    const float* w_q = (const float*)d_in[1];
    const float* b_q = (const float*)d_in[2];
    const float* w_k = (const float*)d_in[3];
    const float* b_k = (const float*)d_in[4];
    const float* w_v = (const float*)d_in[5];
    const float* b_v = (const float*)d_in[6];
    const float* w_o = (const float*)d_in[7];
    const float* b_o = (const float*)d_in[8];
    float* out = (float*)d_out;

    __half *qb, *kb, *vb, *ab, *wt;
    cudaGetSymbolAddress((void**)&qb, g_q);
    cudaGetSymbolAddress((void**)&kb, g_k);
    cudaGetSymbolAddress((void**)&vb, g_v);
    cudaGetSymbolAddress((void**)&ab, g_a);
    cudaGetSymbolAddress((void**)&wt, g_w);

    cudaFuncSetAttribute(gemm_mma<true>,
                         cudaFuncAttributeMaxDynamicSharedMemorySize, GSMEM);
    cudaFuncSetAttribute(gemm_mma<false>,
                         cudaFuncAttributeMaxDynamicSharedMemorySize, GSMEM);
    cudaFuncSetAttribute(attn_mma,
                         cudaFuncAttributeMaxDynamicSharedMemorySize, ASMEM);

    // 1) fused prep: activation convert + weight transpose (one launch)
    prep_kernel<<<PREP_BLOCKS, 256>>>(hs, ab, w_q, w_k, w_v, w_o, wt);

    // 2) fused QKV GEMM: 3 matrices x 8 N-tiles(128) x 128 M-tiles -> fp16
    gemm_mma<true><<<dim3(24, 128), 128, GSMEM>>>(
        ab, wt, 0, b_q, b_k, b_v, qb, kb, vb);

    // 3) HMMA neighborhood attention (fp16 in, fp16 out into A operand)
    attn_mma<<<BATCH * NHEADS * (SEQ / 128), 256, ASMEM>>>(qb, kb, vb, ab);

    // 4) O projection -> fp32 output
    gemm_mma<false><<<dim3(8, 128), 128, GSMEM>>>(
        ab, wt, 3, b_o, b_o, b_o, out, out, out);
}

// round 16
// speedup vs baseline: 1.1078x; 1.1078x over previous
#include <cuda_runtime.h>
#include <cuda_fp16.h>
#include <math.h>
#include <stdint.h>

// ---------------------------------------------------------------------------
// Problem constants
// ---------------------------------------------------------------------------
#define BATCH     2
#define SEQ       8192
#define HID       1024
#define NHEADS    16
#define HDIM      64
#define KWIN      7
#define ATT_SCALE 0.125f
#define M_ROWS    (BATCH * SEQ)     // 16384

// ---------------------------------------------------------------------------
// Scratch (__device__ globals: allowed, no runtime allocation)
// ---------------------------------------------------------------------------
__device__ __half g_q[(size_t)M_ROWS * HID];
__device__ __half g_k[(size_t)M_ROWS * HID];
__device__ __half g_v[(size_t)M_ROWS * HID];
__device__ __half g_a[(size_t)M_ROWS * HID];      // fp16 A operand (reused)
__device__ __half g_w[(size_t)4 * HID * HID];     // transposed [n][k], fp16

// ---------------------------------------------------------------------------
// PTX helpers (base sm_103 target — NO 'a'-gated features)
// ---------------------------------------------------------------------------
__device__ __forceinline__ uint32_t smem_u32(const void* p) {
    uint32_t a;
    asm("{ .reg .u64 t; cvta.to.shared.u64 t, %1; cvt.u32.u64 %0, t; }"
        : "=r"(a) : "l"(p));
    return a;
}
__device__ __forceinline__ void cp16(uint32_t s, const void* g) {
    asm volatile("cp.async.cg.shared.global [%0], [%1], 16;"
                 :: "r"(s), "l"(g));
}
__device__ __forceinline__ void ldsm_x4(uint32_t* r, uint32_t addr) {
    asm volatile("ldmatrix.sync.aligned.m8n8.x4.shared.b16 {%0,%1,%2,%3}, [%4];"
                 : "=r"(r[0]), "=r"(r[1]), "=r"(r[2]), "=r"(r[3]) : "r"(addr));
}
__device__ __forceinline__ void ldsm_x4_t(uint32_t* r, uint32_t addr) {
    asm volatile("ldmatrix.sync.aligned.m8n8.x4.trans.shared.b16 {%0,%1,%2,%3}, [%4];"
                 : "=r"(r[0]), "=r"(r[1]), "=r"(r[2]), "=r"(r[3]) : "r"(addr));
}
__device__ __forceinline__ void mma16816(float* d, const uint32_t* a,
                                         const uint32_t* b) {
    asm volatile(
        "mma.sync.aligned.m16n8k16.row.col.f32.f16.f16.f32 "
        "{%0,%1,%2,%3}, {%4,%5,%6,%7}, {%8,%9}, {%0,%1,%2,%3};"
        : "+f"(d[0]), "+f"(d[1]), "+f"(d[2]), "+f"(d[3])
        : "r"(a[0]), "r"(a[1]), "r"(a[2]), "r"(a[3]), "r"(b[0]), "r"(b[1]));
}

// ---------------------------------------------------------------------------
// GEMM config: 128x128 CTA tile, BK=32, 4-stage cp.async ring, 128 threads
// (4 warps, 2x2 grid of 64x64 warp tiles), 2 CTAs per SM.  [R14 verified]
// New in R16: B-fragment double buffer across ks — the ks=1 ldsm burst is
// issued before the ks=0 MMA block and hides under 32 MMAs.
// ---------------------------------------------------------------------------
#define PITCH   80
#define TILE_A  (128 * PITCH)           // 10240
#define OFF_B   TILE_A
#define BUFB    (2 * TILE_A)            // 20480 per stage (A + B)
#define NSTAGE  4
#define SMEMB   (NSTAGE * BUFB)         // 81920

__device__ __forceinline__ void load_chunk(
    uint32_t base, int tid, int k0, int m0, int n0,
    const __half* __restrict__ A, const __half* __restrict__ B)
{
#pragma unroll
    for (int r = 0; r < 4; r++) {   // A: 128 rows x 64B = 512 cp16
        int idx = tid + r * 128;
        int row = idx >> 2, c = idx & 3;
        uint32_t so = (uint32_t)(row * PITCH + c * 16);
        size_t go = (size_t)(m0 + row) * HID + k0 + c * 8;
        cp16(base + so, A + go);
    }
#pragma unroll
    for (int r = 0; r < 4; r++) {   // B: 128 rows x 64B = 512 cp16
        int idx = tid + r * 128;
        int row = idx >> 2, c = idx & 3;
        uint32_t so = (uint32_t)(row * PITCH + c * 16);
        size_t go = (size_t)(n0 + row) * HID + k0 + c * 8;
        cp16(base + OFF_B + so, B + go);
    }
    asm volatile("cp.async.commit_group;" ::: "memory");
}

// C[m][n] = sum_k A[m][k]*Wt[n][k] + bias[n], single-pass fp16 HMMA.
// grid.x: (matrix_within_launch << 3) | n_tile;  grid.y: m_tile
template <bool HALF_OUT>
__global__ void __launch_bounds__(128, 2)
gemm_mma(const __half* __restrict__ A, const __half* __restrict__ W,
         int mat_base,
         const float* __restrict__ bias0, const float* __restrict__ bias1,
         const float* __restrict__ bias2,
         void* __restrict__ c0v, void* __restrict__ c1v, void* __restrict__ c2v)
{
    extern __shared__ char smem[];
    const uint32_t sb = smem_u32(smem);
    const int tid  = threadIdx.x;
    const int lane = tid & 31;
    const int wid  = tid >> 5;          // 0..3
    const int wm   = wid >> 1;          // 0..1 -> 64-row slab
    const int wn   = wid & 1;           // 0..1 -> 64-col slab
    const int mi_  = blockIdx.x >> 3;   // matrix within launch
    const int n0   = (blockIdx.x & 7) * 128;
    const int m0   = blockIdx.y * 128;

    const __half* B = W + (size_t)(mat_base + mi_) * HID * HID;
    const float* bias = (mi_ == 0) ? bias0 : ((mi_ == 1) ? bias1 : bias2);
    void* Cv = (mi_ == 0) ? c0v : ((mi_ == 1) ? c1v : c2v);

    float acc[4][8][4];                 // 64x64 warp tile: mi x ni x frag
#pragma unroll
    for (int i = 0; i < 4; i++)
#pragma unroll
        for (int j = 0; j < 8; j++)
#pragma unroll
            for (int r = 0; r < 4; r++) acc[i][j][r] = 0.0f;

    load_chunk(sb,            tid, 0,  m0, n0, A, B);
    load_chunk(sb + BUFB,     tid, 32, m0, n0, A, B);
    load_chunk(sb + 2 * BUFB, tid, 64, m0, n0, A, B);

    const int mrow = lane >> 3;
    const int jrow = lane & 7;
    const uint32_t a_off = (uint32_t)((wm * 64 + (mrow & 1) * 8 + jrow) * PITCH
                                      + (mrow >> 1) * 16);
    const uint32_t b_off = (uint32_t)((wn * 64 + (mrow >> 1) * 8 + jrow) * PITCH
                                      + (mrow & 1) * 16) + OFF_B;

    const int NCHUNK = HID / 32;        // 32
    int st = 0;

    for (int ck = 0; ck < NCHUNK; ck++) {
        if (ck <= NCHUNK - 3)      asm volatile("cp.async.wait_group 2;" ::: "memory");
        else if (ck == NCHUNK - 2) asm volatile("cp.async.wait_group 1;" ::: "memory");
        else                       asm volatile("cp.async.wait_group 0;" ::: "memory");
        __syncthreads();

        if (ck + 3 < NCHUNK) {
            int ls = st + 3; if (ls >= NSTAGE) ls -= NSTAGE;
            load_chunk(sb + ls * BUFB, tid, (ck + 3) * 32, m0, n0, A, B);
        }

        const uint32_t base = sb + st * BUFB;

        // preload ks=0 B fragments
        uint32_t bf[2][4][4];
#pragma unroll
        for (int nj = 0; nj < 4; nj++)
            ldsm_x4(bf[0][nj], base + b_off + nj * 16 * PITCH);

#pragma unroll
        for (int ks = 0; ks < 2; ks++) {
            const uint32_t kb = ks * 32;
            // issue next ks's B-ldsm burst early: hides under this ks's MMAs
            if (ks == 0) {
#pragma unroll
                for (int nj = 0; nj < 4; nj++)
                    ldsm_x4(bf[1][nj], base + b_off + nj * 16 * PITCH + 32);
            }
#pragma unroll
            for (int mi = 0; mi < 4; mi++) {
                uint32_t ah[4];
                ldsm_x4(ah, base + a_off + mi * 16 * PITCH + kb);
#pragma unroll
                for (int ni = 0; ni < 8; ni++)
                    mma16816(acc[mi][ni], ah, &bf[ks][ni >> 1][(ni & 1) * 2]);
            }
        }
        if (++st == NSTAGE) st = 0;
    }

    const int grp = lane >> 2, t4 = lane & 3;
#pragma unroll
    for (int ni = 0; ni < 8; ni++) {
        const int col = n0 + wn * 64 + ni * 8 + t4 * 2;
        const float bv0 = bias[col], bv1 = bias[col + 1];
#pragma unroll
        for (int mi = 0; mi < 4; mi++) {
            const int r0 = m0 + wm * 64 + mi * 16 + grp;
            if (HALF_OUT) {
                __half* C = (__half*)Cv;
                __half2 p0 = __floats2half2_rn(acc[mi][ni][0] + bv0,
                                               acc[mi][ni][1] + bv1);
                __half2 p1 = __floats2half2_rn(acc[mi][ni][2] + bv0,
                                               acc[mi][ni][3] + bv1);
                *(uint32_t*)(C + (size_t)r0 * HID + col)       = *(uint32_t*)&p0;
                *(uint32_t*)(C + (size_t)(r0 + 8) * HID + col) = *(uint32_t*)&p1;
            } else {
                float* C = (float*)Cv;
                *(float2*)(C + (size_t)r0 * HID + col) =
                    make_float2(acc[mi][ni][0] + bv0, acc[mi][ni][1] + bv1);
                *(float2*)(C + (size_t)(r0 + 8) * HID + col) =
                    make_float2(acc[mi][ni][2] + bv0, acc[mi][ni][3] + bv1);
            }
        }
    }
}

// ---------------------------------------------------------------------------
// Fused prep: blocks [0,16384) convert activations fp32->fp16;
// blocks [16384,20480) transpose+round the 4 weight matrices.
// ---------------------------------------------------------------------------
#define CONV_BLOCKS 16384
#define PREP_BLOCKS (CONV_BLOCKS + 4096)

__global__ void __launch_bounds__(256)
prep_kernel(const float* __restrict__ x, __half* __restrict__ y,
            const float* __restrict__ w0, const float* __restrict__ w1,
            const float* __restrict__ w2, const float* __restrict__ w3,
            __half* __restrict__ wt)
{
    __shared__ float t[32][33];
    if (blockIdx.x < CONV_BLOCKS) {
        size_t i = ((size_t)blockIdx.x * 256 + threadIdx.x) * 4;
        float4 v = *(const float4*)(x + i);
        __half2 p0 = __floats2half2_rn(v.x, v.y);
        __half2 p1 = __floats2half2_rn(v.z, v.w);
        *(uint2*)(y + i) = make_uint2(*(uint32_t*)&p0, *(uint32_t*)&p1);
    } else {
        const int bid = blockIdx.x - CONV_BLOCKS;
        const int z = bid >> 10;
        const int rem = bid & 1023;
        const int n0 = (rem & 31) * 32, k0 = (rem >> 5) * 32;
        const float* W = (z == 0) ? w0 : ((z == 1) ? w1 : ((z == 2) ? w2 : w3));
        const int tx = threadIdx.x & 31, ty = threadIdx.x >> 5;
#pragma unroll
        for (int r = 0; r < 4; r++)
            t[ty + r * 8][tx] = W[(size_t)(k0 + ty + r * 8) * HID + n0 + tx];
        __syncthreads();
        const size_t base = (size_t)z * HID * HID;
#pragma unroll
        for (int r = 0; r < 4; r++) {
            int n = n0 + ty + r * 8;
            int k = k0 + tx;
            wt[base + (size_t)n * HID + k] = __float2half_rn(t[tx][ty + r * 8]);
        }
    }
}

// ---------------------------------------------------------------------------
// HMMA neighborhood attention (two-group staging; unchanged from R12-R14)
// ---------------------------------------------------------------------------
#define PV      144
#define ASMEM   ((128 + 144 + 144) * PV)    // 59904

__global__ void __launch_bounds__(256)
attn_mma(const __half* __restrict__ Q, const __half* __restrict__ K,
         const __half* __restrict__ V, __half* __restrict__ O)
{
    extern __shared__ char smem[];
    const uint32_t sbq = smem_u32(smem);
    const uint32_t sbk = sbq + 128 * PV;
    const uint32_t sbv = sbk + 144 * PV;
    const int tid = threadIdx.x, lane = tid & 31, w = tid >> 5;
    const int bh = blockIdx.x >> 6;
    const int s0 = (blockIdx.x & 63) * 128;
    const int b = bh >> 4, h = bh & 15;
    const size_t rowbase = ((size_t)b * SEQ) * HID + h * HDIM;

#pragma unroll
    for (int r = 0; r < 4; r++) {
        int idx = tid + r * 256;
        int row = idx >> 3, c = idx & 7;
        cp16(sbq + row * PV + c * 16,
             Q + rowbase + (size_t)(s0 + row) * HID + c * 8);
    }
    for (int idx = tid; idx < 1152; idx += 256) {
        int row = idx >> 3, c = idx & 7;
        int sk = s0 + row - 3;
        sk = sk < 0 ? 0 : (sk >= SEQ ? SEQ - 1 : sk);
        cp16(sbk + row * PV + c * 16, K + rowbase + (size_t)sk * HID + c * 8);
    }
    asm volatile("cp.async.commit_group;" ::: "memory");
    for (int idx = tid; idx < 1152; idx += 256) {
        int row = idx >> 3, c = idx & 7;
        int sk = s0 + row - 3;
        sk = sk < 0 ? 0 : (sk >= SEQ ? SEQ - 1 : sk);
        cp16(sbv + row * PV + c * 16, V + rowbase + (size_t)sk * HID + c * 8);
    }
    asm volatile("cp.async.commit_group;" ::: "memory");
    asm volatile("cp.async.wait_group 1;" ::: "memory");
    __syncthreads();

    const int mrow = lane >> 3, jrow = lane & 7;
    const int grp = lane >> 2, t4 = lane & 3;
    const uint32_t aq_off = sbq + (uint32_t)((w * 16 + (mrow & 1) * 8 + jrow) * PV
                                             + (mrow >> 1) * 16);
    const uint32_t bk_off = sbk + (uint32_t)((w * 16 + (mrow >> 1) * 8 + jrow) * PV
                                             + (mrow & 1) * 16);
    const uint32_t bv_off = sbv + (uint32_t)((w * 16 + (mrow & 1) * 8 + jrow) * PV
                                             + (mrow >> 1) * 16);

    float accS[4][4];
#pragma unroll
    for (int i = 0; i < 4; i++)
#pragma unroll
        for (int r = 0; r < 4; r++) accS[i][r] = 0.0f;

#pragma unroll
    for (int ks = 0; ks < 4; ks++) {
        uint32_t aq[4], bk0[4], bk1[4];
        ldsm_x4(aq,  aq_off + ks * 32);
        ldsm_x4(bk0, bk_off + ks * 32);
        ldsm_x4(bk1, bk_off + 16 * PV + ks * 32);
        mma16816(accS[0], aq, &bk0[0]);
        mma16816(accS[1], aq, &bk0[2]);
        mma16816(accS[2], aq, &bk1[0]);
        mma16816(accS[3], aq, &bk1[2]);
    }

    const float NEG = -1e30f;
#pragma unroll
    for (int ni = 0; ni < 4; ni++)
#pragma unroll
        for (int pp = 0; pp < 4; pp++) {
            int r = (pp >= 2) ? grp + 8 : grp;
            int c = 8 * ni + 2 * t4 + (pp & 1);
            int sk = s0 + 16 * w + c - 3;
            bool ok = (c >= r) && (c <= r + 6) && (sk >= 0) && (sk < SEQ);
            accS[ni][pp] = ok ? accS[ni][pp] * ATT_SCALE : NEG;
        }

    float m0 = NEG, m1 = NEG;
#pragma unroll
    for (int ni = 0; ni < 4; ni++) {
        m0 = fmaxf(m0, fmaxf(accS[ni][0], accS[ni][1]));
        m1 = fmaxf(m1, fmaxf(accS[ni][2], accS[ni][3]));
    }
#pragma unroll
    for (int o = 1; o <= 2; o <<= 1) {
        m0 = fmaxf(m0, __shfl_xor_sync(0xffffffffu, m0, o));
        m1 = fmaxf(m1, __shfl_xor_sync(0xffffffffu, m1, o));
    }
    float d0 = 0.0f, d1 = 0.0f;
#pragma unroll
    for (int ni = 0; ni < 4; ni++) {
        accS[ni][0] = __expf(accS[ni][0] - m0);
        accS[ni][1] = __expf(accS[ni][1] - m0);
        accS[ni][2] = __expf(accS[ni][2] - m1);
        accS[ni][3] = __expf(accS[ni][3] - m1);
        d0 += accS[ni][0] + accS[ni][1];
        d1 += accS[ni][2] + accS[ni][3];
    }
#pragma unroll
    for (int o = 1; o <= 2; o <<= 1) {
        d0 += __shfl_xor_sync(0xffffffffu, d0, o);
        d1 += __shfl_xor_sync(0xffffffffu, d1, o);
    }
    const float inv0 = 1.0f / d0, inv1 = 1.0f / d1;

    uint32_t aP[2][4];
#pragma unroll
    for (int ks = 0; ks < 2; ks++) {
        __half2 v0 = __floats2half2_rn(accS[2 * ks][0] * inv0,
                                       accS[2 * ks][1] * inv0);
        __half2 v1 = __floats2half2_rn(accS[2 * ks][2] * inv1,
                                       accS[2 * ks][3] * inv1);
        __half2 v2 = __floats2half2_rn(accS[2 * ks + 1][0] * inv0,
                                       accS[2 * ks + 1][1] * inv0);
        __half2 v3 = __floats2half2_rn(accS[2 * ks + 1][2] * inv1,
                                       accS[2 * ks + 1][3] * inv1);
        aP[ks][0] = *(uint32_t*)&v0;
        aP[ks][1] = *(uint32_t*)&v1;
        aP[ks][2] = *(uint32_t*)&v2;
        aP[ks][3] = *(uint32_t*)&v3;
    }

    asm volatile("cp.async.wait_group 0;" ::: "memory");
    __syncthreads();

    float accO[8][4];
#pragma unroll
    for (int i = 0; i < 8; i++)
#pragma unroll
        for (int r = 0; r < 4; r++) accO[i][r] = 0.0f;

#pragma unroll
    for (int g = 0; g < 4; g++)
#pragma unroll
        for (int ks = 0; ks < 2; ks++) {
            uint32_t bv[4];
            ldsm_x4_t(bv, bv_off + ks * 16 * PV + g * 32);
            mma16816(accO[2 * g],     aP[ks], &bv[0]);
            mma16816(accO[2 * g + 1], aP[ks], &bv[2]);
        }

    const int q0 = s0 + 16 * w;
#pragma unroll
    for (int nf = 0; nf < 8; nf++) {
        int col = 8 * nf + 2 * t4;
        __half2 p0 = __floats2half2_rn(accO[nf][0], accO[nf][1]);
        __half2 p1 = __floats2half2_rn(accO[nf][2], accO[nf][3]);
        *(uint32_t*)(O + rowbase + (size_t)(q0 + grp) * HID + col)     = *(uint32_t*)&p0;
        *(uint32_t*)(O + rowbase + (size_t)(q0 + grp + 8) * HID + col) = *(uint32_t*)&p1;
    }
}

// ---------------------------------------------------------------------------
// Launch
// ---------------------------------------------------------------------------
extern "C" void kernel_launch(void* const* d_in, const int* in_sizes, int n_in,
                              void* d_out, int out_size)
{
    const float* hs  = (const float*)d_in[0];
    const float* w_q = (const float*)d_in[1];
    const float* b_q = (const float*)d_in[2];
    const float* w_k = (const float*)d_in[3];
    const float* b_k = (const float*)d_in[4];
    const float* w_v = (const float*)d_in[5];
    const float* b_v = (const float*)d_in[6];
    const float* w_o = (const float*)d_in[7];
    const float* b_o = (const float*)d_in[8];
    float* out = (float*)d_out;

    __half *qb, *kb, *vb, *ab, *wt;
    cudaGetSymbolAddress((void**)&qb, g_q);
    cudaGetSymbolAddress((void**)&kb, g_k);
    cudaGetSymbolAddress((void**)&vb, g_v);
    cudaGetSymbolAddress((void**)&ab, g_a);
    cudaGetSymbolAddress((void**)&wt, g_w);

    cudaFuncSetAttribute(gemm_mma<true>,
                         cudaFuncAttributeMaxDynamicSharedMemorySize, SMEMB);
    cudaFuncSetAttribute(gemm_mma<false>,
                         cudaFuncAttributeMaxDynamicSharedMemorySize, SMEMB);
    cudaFuncSetAttribute(attn_mma,
                         cudaFuncAttributeMaxDynamicSharedMemorySize, ASMEM);

    // 1) fused prep: activation convert + weight transpose (one launch)
    prep_kernel<<<PREP_BLOCKS, 256>>>(hs, ab, w_q, w_k, w_v, w_o, wt);

    // 2) fused QKV GEMM: 3 matrices x 8 N-tiles(128) x 128 M-tiles -> fp16
    gemm_mma<true><<<dim3(24, 128), 128, SMEMB>>>(
        ab, wt, 0, b_q, b_k, b_v, qb, kb, vb);

    // 3) HMMA neighborhood attention (fp16 in, fp16 out into A operand)
    attn_mma<<<BATCH * NHEADS * (SEQ / 128), 256, ASMEM>>>(qb, kb, vb, ab);

    // 4) O projection -> fp32 output
    gemm_mma<false><<<dim3(8, 128), 128, SMEMB>>>(
        ab, wt, 3, b_o, b_o, b_o, out, out, out);
}